// round 1
// baseline (speedup 1.0000x reference)
#include <cuda_runtime.h>

#define NN 100000
#define EE 1600000
#define INC 128
#define HIDC 256
#define OUTC 64
#define FEPS 1e-5f

// ---------------- scratch (static device allocations; no cudaMalloc) --------
__device__ int   g_is64;
__device__ float g_deg[NN];
__device__ float g_deginv[NN];
__device__ float g_msg[(size_t)NN * HIDC];   // reused: 128-d then 256-d aggregates
__device__ float g_h1[(size_t)NN * HIDC];
__device__ float g_h2[(size_t)NN * HIDC];
__device__ float g_t[(size_t)NN * OUTC];     // h2 @ Wcl
__device__ float g_r[(size_t)NN * OUTC];     // h2 @ Wcr + bcl
__device__ float g_aggt[(size_t)NN * OUTC];  // segment_sum of g_t

// ---------------- helpers ---------------------------------------------------
__device__ __forceinline__ int load_idx(const void* base, long long i) {
    if (g_is64) return (int)((const long long*)base)[i];
    return ((const int*)base)[i];
}

// Detect whether edge_index is int64 (high words all zero for sampled entries)
// or int32. Values are uniform in [0, 100000); 32 consecutive odd-word zeros
// under int32 has probability ~1e-160.
__global__ void k_detect(const int* e32) {
    int is64 = 1;
    for (int i = 0; i < 32; i++)
        if (e32[2 * i + 1] != 0) is64 = 0;
    g_is64 = is64;
}

__global__ void k_zero(float* p, long long n) {
    long long i = (long long)blockIdx.x * blockDim.x + threadIdx.x;
    long long stride = (long long)gridDim.x * blockDim.x;
    for (; i < n; i += stride) p[i] = 0.0f;
}

__global__ void k_deg(const void* eidx) {
    int e = blockIdx.x * blockDim.x + threadIdx.x;
    if (e < EE) {
        int d = load_idx(eidx, (long long)EE + e);
        atomicAdd(&g_deg[d], 1.0f);
    }
}

__global__ void k_deginv() {
    int i = blockIdx.x * blockDim.x + threadIdx.x;
    if (i < NN) {
        float dg = g_deg[i];
        g_deginv[i] = (dg > 0.0f) ? (1.0f / dg) : 0.0f;
    }
}

// Scatter-add aggregation: one thread per (edge, float4-chunk).
// D4 = feature_dim / 4 (compile-time so /,% become shifts/masks).
template <int D4>
__global__ void k_agg(const void* __restrict__ eidx,
                      const float* __restrict__ feat,
                      float* __restrict__ acc) {
    long long i = (long long)blockIdx.x * blockDim.x + threadIdx.x;
    long long total = (long long)EE * D4;
    if (i >= total) return;
    int e = (int)(i / D4);
    int c = (int)(i % D4);
    int s = load_idx(eidx, e);
    int d = load_idx(eidx, (long long)EE + e);
    float4 v = ((const float4*)feat)[(long long)s * D4 + c];
    float* p = acc + ((long long)d * D4 + c) * 4;
    atomicAdd(p + 0, v.x);
    atomicAdd(p + 1, v.y);
    atomicAdd(p + 2, v.z);
    atomicAdd(p + 3, v.w);
}

// ---------------- fused GEMM ------------------------------------------------
// C[row, col] = (SCALE_A1 ? deginv[row] : 1) * (A1 @ B1)[row, col]
//            (+ (A2 @ B2)[row, col] if HAS_A2)
//            (+ bias[col] if HAS_BIAS)
//  then optional BN (gamma, beta, rm, rv) + ReLU.
// Tiled: BM=BN=64, BK=16, 256 threads, 4x4 per-thread microtile.
template <int K, bool SCALE_A1, bool HAS_A2, bool HAS_BIAS, bool BN_RELU>
__global__ void k_gemm(const float* __restrict__ A1,
                       const float* __restrict__ A2,
                       const float* __restrict__ B1,
                       const float* __restrict__ B2,
                       const float* __restrict__ bias,
                       const float* __restrict__ gamma,
                       const float* __restrict__ beta,
                       const float* __restrict__ rm,
                       const float* __restrict__ rv,
                       float* __restrict__ C, int nout) {
    __shared__ float As[16][64];
    __shared__ float Bs[16][68];  // pad to soften stride-4 conflicts

    const int bm = blockIdx.x * 64;
    const int bn = blockIdx.y * 64;
    const int tid = threadIdx.x;
    const int tx = tid & 15;   // -> 4 cols
    const int ty = tid >> 4;   // -> 4 rows

    float acc[4][4];
#pragma unroll
    for (int i = 0; i < 4; i++)
#pragma unroll
        for (int j = 0; j < 4; j++) acc[i][j] = 0.0f;

    for (int pass = 0; pass < (HAS_A2 ? 2 : 1); pass++) {
        const float* A = (pass == 0) ? A1 : A2;
        const float* B = (pass == 0) ? B1 : B2;
        const bool scale = SCALE_A1 && (pass == 0);

        for (int k0 = 0; k0 < K; k0 += 16) {
            // load A tile (64 rows x 16 k), coalesced along k
#pragma unroll
            for (int i = 0; i < 4; i++) {
                int idx = tid + i * 256;
                int k = idx & 15;
                int m = idx >> 4;
                int row = bm + m;
                float v = 0.0f;
                if (row < NN) {
                    v = A[(long long)row * K + k0 + k];
                    if (scale) v *= g_deginv[row];
                }
                As[k][m] = v;
            }
            // load B tile (16 k x 64 cols), coalesced along n
#pragma unroll
            for (int i = 0; i < 4; i++) {
                int idx = tid + i * 256;
                int n = idx & 63;
                int k = idx >> 6;
                Bs[k][n] = B[(long long)(k0 + k) * nout + bn + n];
            }
            __syncthreads();

#pragma unroll
            for (int k = 0; k < 16; k++) {
                float ra[4], rb[4];
#pragma unroll
                for (int i = 0; i < 4; i++) ra[i] = As[k][ty * 4 + i];
#pragma unroll
                for (int j = 0; j < 4; j++) rb[j] = Bs[k][tx * 4 + j];
#pragma unroll
                for (int i = 0; i < 4; i++)
#pragma unroll
                    for (int j = 0; j < 4; j++) acc[i][j] += ra[i] * rb[j];
            }
            __syncthreads();
        }
    }

#pragma unroll
    for (int i = 0; i < 4; i++) {
        int row = bm + ty * 4 + i;
        if (row >= NN) continue;
#pragma unroll
        for (int j = 0; j < 4; j++) {
            int col = bn + tx * 4 + j;
            float v = acc[i][j];
            if (HAS_BIAS) v += bias[col];
            if (BN_RELU) {
                v = (v - rm[col]) * rsqrtf(rv[col] + FEPS) * gamma[col] + beta[col];
                v = fmaxf(v, 0.0f);
            }
            C[(long long)row * nout + col] = v;
        }
    }
}

// out = deginv * aggt + r   (bcl already folded into r)
__global__ void k_combine(float* __restrict__ out) {
    long long i = (long long)blockIdx.x * blockDim.x + threadIdx.x;
    if (i < (long long)NN * OUTC) {
        int row = (int)(i >> 6);  // OUTC = 64
        out[i] = g_deginv[row] * g_aggt[i] + g_r[i];
    }
}

// ---------------- launch ----------------------------------------------------
extern "C" void kernel_launch(void* const* d_in, const int* in_sizes, int n_in,
                              void* d_out, int out_size) {
    const float* x    = (const float*)d_in[0];
    const void*  eidx = d_in[1];
    const float* W1l  = (const float*)d_in[2];
    const float* b1l  = (const float*)d_in[3];
    const float* W1r  = (const float*)d_in[4];
    const float* g1   = (const float*)d_in[5];
    const float* be1  = (const float*)d_in[6];
    const float* rm1  = (const float*)d_in[7];
    const float* rv1  = (const float*)d_in[8];
    const float* W2l  = (const float*)d_in[9];
    const float* b2l  = (const float*)d_in[10];
    const float* W2r  = (const float*)d_in[11];
    const float* g2   = (const float*)d_in[12];
    const float* be2  = (const float*)d_in[13];
    const float* rm2  = (const float*)d_in[14];
    const float* rv2  = (const float*)d_in[15];
    const float* Wcl  = (const float*)d_in[16];
    const float* bcl  = (const float*)d_in[17];
    const float* Wcr  = (const float*)d_in[18];
    float* out = (float*)d_out;

    float* p_deg;    cudaGetSymbolAddress((void**)&p_deg, g_deg);
    float* p_msg;    cudaGetSymbolAddress((void**)&p_msg, g_msg);
    float* p_h1;     cudaGetSymbolAddress((void**)&p_h1, g_h1);
    float* p_h2;     cudaGetSymbolAddress((void**)&p_h2, g_h2);
    float* p_t;      cudaGetSymbolAddress((void**)&p_t, g_t);
    float* p_r;      cudaGetSymbolAddress((void**)&p_r, g_r);
    float* p_aggt;   cudaGetSymbolAddress((void**)&p_aggt, g_aggt);

    // 0) dtype detection for edge_index (int32 vs int64)
    k_detect<<<1, 1>>>((const int*)eidx);

    // 1) degrees
    k_zero<<<512, 256>>>(p_deg, NN);
    k_deg<<<(EE + 255) / 256, 256>>>(eidx);
    k_deginv<<<(NN + 255) / 256, 256>>>();

    const int MBLK = (NN + 63) / 64;

    // 2) layer 1: aggregate x (128-d), then fused GEMM + BN + ReLU -> h1
    k_zero<<<2048, 256>>>(p_msg, (long long)NN * INC);
    {
        long long total = (long long)EE * (INC / 4);
        k_agg<INC / 4><<<(int)((total + 255) / 256), 256>>>(eidx, x, p_msg);
    }
    k_gemm<INC, true, true, true, true>
        <<<dim3(MBLK, HIDC / 64), 256>>>(p_msg, x, W1l, W1r, b1l,
                                         g1, be1, rm1, rv1, p_h1, HIDC);

    // 3) layer 2: aggregate h1 (256-d), fused GEMM + BN + ReLU -> h2
    k_zero<<<4096, 256>>>(p_msg, (long long)NN * HIDC);
    {
        long long total = (long long)EE * (HIDC / 4);
        k_agg<HIDC / 4><<<(int)((total + 255) / 256), 256>>>(eidx, p_h1, p_msg);
    }
    k_gemm<HIDC, true, true, true, true>
        <<<dim3(MBLK, HIDC / 64), 256>>>(p_msg, p_h1, W2l, W2r, b2l,
                                         g2, be2, rm2, rv2, p_h2, HIDC);

    // 4) layer 3 (transform-first: aggregation is linear, so aggregate the
    //    64-d transformed features instead of the 256-d hidden state)
    k_gemm<HIDC, false, false, false, false>
        <<<dim3(MBLK, OUTC / 64), 256>>>(p_h2, nullptr, Wcl, nullptr, nullptr,
                                         nullptr, nullptr, nullptr, nullptr,
                                         p_t, OUTC);
    k_gemm<HIDC, false, false, true, false>
        <<<dim3(MBLK, OUTC / 64), 256>>>(p_h2, nullptr, Wcr, nullptr, bcl,
                                         nullptr, nullptr, nullptr, nullptr,
                                         p_r, OUTC);
    k_zero<<<2048, 256>>>(p_aggt, (long long)NN * OUTC);
    {
        long long total = (long long)EE * (OUTC / 4);
        k_agg<OUTC / 4><<<(int)((total + 255) / 256), 256>>>(eidx, p_t, p_aggt);
    }
    k_combine<<<(int)(((long long)NN * OUTC + 255) / 256), 256>>>(out);
}

// round 2
// speedup vs baseline: 1.5994x; 1.5994x over previous
#include <cuda_runtime.h>

#define NN 100000
#define EE 1600000
#define INC 128
#define HIDC 256
#define OUTC 64
#define FEPS 1e-5f
#define NBLK1 ((NN + 255) / 256)   // 391 scan blocks

// ---------------- scratch (static device allocations; no cudaMalloc) --------
__device__ int   g_is64;
__device__ int   g_degi[NN];
__device__ int   g_incl[NN];       // block-inclusive scan of deg
__device__ int   g_bsum[512];      // per-block sums (391 used)
__device__ int   g_boff[512];      // scanned block sums
__device__ int   g_rowptr[NN];
__device__ int   g_cursor[NN];
__device__ int   g_csrc[EE];       // CSR: source node per incoming edge, grouped by dst
__device__ float g_msg[(size_t)NN * HIDC];   // mean-aggregated features (128-d / 256-d)
__device__ float g_h1[(size_t)NN * HIDC];
__device__ float g_h2[(size_t)NN * HIDC];
__device__ float g_t[(size_t)NN * OUTC];     // h2 @ Wcl
__device__ float g_r[(size_t)NN * OUTC];     // h2 @ Wcr + bcl

// ---------------- helpers ---------------------------------------------------
__device__ __forceinline__ int load_idx(const void* base, long long i) {
    if (g_is64) return (int)((const long long*)base)[i];
    return ((const int*)base)[i];
}

// Detect int64 vs int32 edge_index (odd 32-bit words all zero => int64).
__global__ void k_detect(const int* e32) {
    int is64 = 1;
    for (int i = 0; i < 32; i++)
        if (e32[2 * i + 1] != 0) is64 = 0;
    g_is64 = is64;
}

__global__ void k_zeroi(int* p, int n) {
    int i = blockIdx.x * blockDim.x + threadIdx.x;
    if (i < n) p[i] = 0;
}

__global__ void k_degi(const void* eidx) {
    int e = blockIdx.x * blockDim.x + threadIdx.x;
    if (e < EE) {
        int d = load_idx(eidx, (long long)EE + e);
        atomicAdd(&g_degi[d], 1);
    }
}

// ---- 3-kernel exclusive scan over degrees -> row_ptr -----------------------
__global__ void k_scan1() {
    __shared__ int s[256];
    int i = blockIdx.x * 256 + threadIdx.x;
    int v = (i < NN) ? g_degi[i] : 0;
    s[threadIdx.x] = v;
    __syncthreads();
#pragma unroll
    for (int off = 1; off < 256; off <<= 1) {
        int t = (threadIdx.x >= off) ? s[threadIdx.x - off] : 0;
        __syncthreads();
        s[threadIdx.x] += t;
        __syncthreads();
    }
    if (i < NN) g_incl[i] = s[threadIdx.x];
    if (threadIdx.x == 255) g_bsum[blockIdx.x] = s[255];
}

__global__ void k_scan2() {
    __shared__ int s[512];
    int tid = threadIdx.x;
    s[tid] = (tid < NBLK1) ? g_bsum[tid] : 0;
    __syncthreads();
#pragma unroll
    for (int off = 1; off < 512; off <<= 1) {
        int t = (tid >= off) ? s[tid - off] : 0;
        __syncthreads();
        s[tid] += t;
        __syncthreads();
    }
    g_boff[tid] = s[tid];
}

__global__ void k_scan3() {
    int i = blockIdx.x * 256 + threadIdx.x;
    if (i < NN) {
        int off = (blockIdx.x > 0) ? g_boff[blockIdx.x - 1] : 0;
        int start = off + g_incl[i] - g_degi[i];
        g_rowptr[i] = start;
        g_cursor[i] = start;
    }
}

__global__ void k_fill(const void* eidx) {
    int e = blockIdx.x * blockDim.x + threadIdx.x;
    if (e < EE) {
        int s = load_idx(eidx, e);
        int d = load_idx(eidx, (long long)EE + e);
        int pos = atomicAdd(&g_cursor[d], 1);
        g_csrc[pos] = s;
    }
}

// ---- gather-based mean aggregation: one warp per destination node ----------
// D = 32*VEC features; lane l accumulates channels {32v + l}. Coalesced loads,
// no atomics. Writes mean (deg_inv folded in); optionally adds `extra`.
template <int VEC, bool ADD_EXTRA>
__global__ void k_agg(const float* __restrict__ feat,
                      const float* __restrict__ extra,
                      float* __restrict__ outp) {
    const int D = 32 * VEC;
    int warp = (blockIdx.x * blockDim.x + threadIdx.x) >> 5;
    int lane = threadIdx.x & 31;
    if (warp >= NN) return;
    int start = g_rowptr[warp];
    int dg = g_degi[warp];
    float acc[VEC];
#pragma unroll
    for (int v = 0; v < VEC; v++) acc[v] = 0.0f;
    for (int j = 0; j < dg; j++) {
        int s = g_csrc[start + j];
        const float* base = feat + (long long)s * D + lane;
#pragma unroll
        for (int v = 0; v < VEC; v++) acc[v] += base[v * 32];
    }
    float inv = (dg > 0) ? (1.0f / (float)dg) : 0.0f;
    float* op = outp + (long long)warp * D + lane;
    const float* ep = ADD_EXTRA ? (extra + (long long)warp * D + lane) : nullptr;
#pragma unroll
    for (int v = 0; v < VEC; v++) {
        float o = acc[v] * inv;
        if (ADD_EXTRA) o += ep[v * 32];
        op[v * 32] = o;
    }
}

// ---------------- fused GEMM ------------------------------------------------
// C = A1 @ B1 (+ A2 @ B2) (+ bias), then optional BN + ReLU.
// Tiled: BM=BN=64, BK=16, 256 threads, 4x4 microtile.
template <int K, bool HAS_A2, bool HAS_BIAS, bool BN_RELU>
__global__ void k_gemm(const float* __restrict__ A1,
                       const float* __restrict__ A2,
                       const float* __restrict__ B1,
                       const float* __restrict__ B2,
                       const float* __restrict__ bias,
                       const float* __restrict__ gamma,
                       const float* __restrict__ beta,
                       const float* __restrict__ rm,
                       const float* __restrict__ rv,
                       float* __restrict__ C, int nout) {
    __shared__ float As[16][64];
    __shared__ float Bs[16][68];

    const int bm = blockIdx.x * 64;
    const int bn = blockIdx.y * 64;
    const int tid = threadIdx.x;
    const int tx = tid & 15;
    const int ty = tid >> 4;

    float acc[4][4];
#pragma unroll
    for (int i = 0; i < 4; i++)
#pragma unroll
        for (int j = 0; j < 4; j++) acc[i][j] = 0.0f;

    for (int pass = 0; pass < (HAS_A2 ? 2 : 1); pass++) {
        const float* A = (pass == 0) ? A1 : A2;
        const float* B = (pass == 0) ? B1 : B2;

        for (int k0 = 0; k0 < K; k0 += 16) {
#pragma unroll
            for (int i = 0; i < 4; i++) {
                int idx = tid + i * 256;
                int k = idx & 15;
                int m = idx >> 4;
                int row = bm + m;
                As[k][m] = (row < NN) ? A[(long long)row * K + k0 + k] : 0.0f;
            }
#pragma unroll
            for (int i = 0; i < 4; i++) {
                int idx = tid + i * 256;
                int n = idx & 63;
                int k = idx >> 6;
                Bs[k][n] = B[(long long)(k0 + k) * nout + bn + n];
            }
            __syncthreads();

#pragma unroll
            for (int k = 0; k < 16; k++) {
                float ra[4], rb[4];
#pragma unroll
                for (int i = 0; i < 4; i++) ra[i] = As[k][ty * 4 + i];
#pragma unroll
                for (int j = 0; j < 4; j++) rb[j] = Bs[k][tx * 4 + j];
#pragma unroll
                for (int i = 0; i < 4; i++)
#pragma unroll
                    for (int j = 0; j < 4; j++) acc[i][j] += ra[i] * rb[j];
            }
            __syncthreads();
        }
    }

#pragma unroll
    for (int i = 0; i < 4; i++) {
        int row = bm + ty * 4 + i;
        if (row >= NN) continue;
#pragma unroll
        for (int j = 0; j < 4; j++) {
            int col = bn + tx * 4 + j;
            float v = acc[i][j];
            if (HAS_BIAS) v += bias[col];
            if (BN_RELU) {
                v = (v - rm[col]) * rsqrtf(rv[col] + FEPS) * gamma[col] + beta[col];
                v = fmaxf(v, 0.0f);
            }
            C[(long long)row * nout + col] = v;
        }
    }
}

// ---------------- launch ----------------------------------------------------
extern "C" void kernel_launch(void* const* d_in, const int* in_sizes, int n_in,
                              void* d_out, int out_size) {
    const float* x    = (const float*)d_in[0];
    const void*  eidx = d_in[1];
    const float* W1l  = (const float*)d_in[2];
    const float* b1l  = (const float*)d_in[3];
    const float* W1r  = (const float*)d_in[4];
    const float* g1   = (const float*)d_in[5];
    const float* be1  = (const float*)d_in[6];
    const float* rm1  = (const float*)d_in[7];
    const float* rv1  = (const float*)d_in[8];
    const float* W2l  = (const float*)d_in[9];
    const float* b2l  = (const float*)d_in[10];
    const float* W2r  = (const float*)d_in[11];
    const float* g2   = (const float*)d_in[12];
    const float* be2  = (const float*)d_in[13];
    const float* rm2  = (const float*)d_in[14];
    const float* rv2  = (const float*)d_in[15];
    const float* Wcl  = (const float*)d_in[16];
    const float* bcl  = (const float*)d_in[17];
    const float* Wcr  = (const float*)d_in[18];
    float* out = (float*)d_out;

    int*   p_degi; cudaGetSymbolAddress((void**)&p_degi, g_degi);
    float* p_msg;  cudaGetSymbolAddress((void**)&p_msg, g_msg);
    float* p_h1;   cudaGetSymbolAddress((void**)&p_h1, g_h1);
    float* p_h2;   cudaGetSymbolAddress((void**)&p_h2, g_h2);
    float* p_t;    cudaGetSymbolAddress((void**)&p_t, g_t);
    float* p_r;    cudaGetSymbolAddress((void**)&p_r, g_r);

    // 0) dtype detection
    k_detect<<<1, 1>>>((const int*)eidx);

    // 1) CSR build: degrees -> scan -> fill
    k_zeroi<<<NBLK1, 256>>>(p_degi, NN);
    k_degi<<<(EE + 255) / 256, 256>>>(eidx);
    k_scan1<<<NBLK1, 256>>>();
    k_scan2<<<1, 512>>>();
    k_scan3<<<NBLK1, 256>>>();
    k_fill<<<(EE + 255) / 256, 256>>>(eidx);

    const int MBLK = (NN + 63) / 64;
    const int AGG_BLOCKS = (NN + 7) / 8;  // 8 warps per 256-thread block

    // 2) layer 1: mean-aggregate x (128-d), fused GEMM + BN + ReLU -> h1
    k_agg<INC / 32, false><<<AGG_BLOCKS, 256>>>(x, nullptr, p_msg);
    k_gemm<INC, true, true, true>
        <<<dim3(MBLK, HIDC / 64), 256>>>(p_msg, x, W1l, W1r, b1l,
                                         g1, be1, rm1, rv1, p_h1, HIDC);

    // 3) layer 2: mean-aggregate h1 (256-d), fused GEMM + BN + ReLU -> h2
    k_agg<HIDC / 32, false><<<AGG_BLOCKS, 256>>>(p_h1, nullptr, p_msg);
    k_gemm<HIDC, true, true, true>
        <<<dim3(MBLK, HIDC / 64), 256>>>(p_msg, p_h1, W2l, W2r, b2l,
                                         g2, be2, rm2, rv2, p_h2, HIDC);

    // 4) layer 3 (transform-first): t = h2@Wcl, r = h2@Wcr + bcl,
    //    out = mean-agg(t) + r  (aggregation is linear -> aggregate 64-d)
    k_gemm<HIDC, false, false, false>
        <<<dim3(MBLK, OUTC / 64), 256>>>(p_h2, nullptr, Wcl, nullptr, nullptr,
                                         nullptr, nullptr, nullptr, nullptr,
                                         p_t, OUTC);
    k_gemm<HIDC, false, true, false>
        <<<dim3(MBLK, OUTC / 64), 256>>>(p_h2, nullptr, Wcr, nullptr, bcl,
                                         nullptr, nullptr, nullptr, nullptr,
                                         p_r, OUTC);
    k_agg<OUTC / 32, true><<<AGG_BLOCKS, 256>>>(p_t, p_r, out);
}

// round 4
// speedup vs baseline: 3.3000x; 2.0633x over previous
#include <cuda_runtime.h>
#include <cuda_bf16.h>
#include <cstdint>

#define NN 100000
#define EE 1600000
#define INC 128
#define HIDC 256
#define OUTC 64
#define FEPS 1e-5f
#define NBLK1 ((NN + 255) / 256)

// ---------------- scratch ----------------------------------------------------
__device__ int   g_is64;
__device__ int   g_degi[NN];
__device__ int   g_incl[NN];
__device__ int   g_bsum[512];
__device__ int   g_boff[512];
__device__ int   g_rowptr[NN];
__device__ int   g_cursor[NN];
__device__ int   g_csrc[EE];
__device__ float g_msg[(size_t)NN * HIDC];
__device__ float g_h1[(size_t)NN * HIDC];
__device__ float g_h2[(size_t)NN * HIDC];
__device__ float g_t[(size_t)NN * OUTC];
__device__ float g_r[(size_t)NN * OUTC];
// bf16 split operand buffers
__device__ __nv_bfloat16 g_a1h[(size_t)NN * HIDC];
__device__ __nv_bfloat16 g_a1l[(size_t)NN * HIDC];
__device__ __nv_bfloat16 g_a2h[(size_t)NN * HIDC];
__device__ __nv_bfloat16 g_a2l[(size_t)NN * HIDC];
// transposed, split weights, [N][K] layout. Wcl/Wcr contiguous -> one [128][256].
#define WO_1L 0
#define WO_1R 32768
#define WO_2L 65536
#define WO_2R 131072
#define WO_CL 196608
#define WO_CR 212992
__device__ __nv_bfloat16 g_wh[229376];
__device__ __nv_bfloat16 g_wl[229376];

// ---------------- PTX helpers ------------------------------------------------
__device__ __forceinline__ uint32_t smem_u32(const void* p) {
    uint32_t a;
    asm("{ .reg .u64 t; cvta.to.shared.u64 t, %1; cvt.u32.u64 %0, t; }"
        : "=r"(a) : "l"(p));
    return a;
}
#define LDSM4(r, addr)                                                          \
    asm volatile("ldmatrix.sync.aligned.m8n8.x4.shared.b16 {%0,%1,%2,%3}, [%4];"\
                 : "=r"((r)[0]), "=r"((r)[1]), "=r"((r)[2]), "=r"((r)[3])       \
                 : "r"(addr))
#define LDSM2(r, addr)                                                          \
    asm volatile("ldmatrix.sync.aligned.m8n8.x2.shared.b16 {%0,%1}, [%2];"      \
                 : "=r"((r)[0]), "=r"((r)[1]) : "r"(addr))
#define MMA16816(d, a, b)                                                       \
    asm volatile("mma.sync.aligned.m16n8k16.row.col.f32.bf16.bf16.f32 "         \
                 "{%0,%1,%2,%3}, {%4,%5,%6,%7}, {%8,%9}, {%0,%1,%2,%3};"        \
                 : "+f"((d)[0]), "+f"((d)[1]), "+f"((d)[2]), "+f"((d)[3])       \
                 : "r"((a)[0]), "r"((a)[1]), "r"((a)[2]), "r"((a)[3]),          \
                   "r"((b)[0]), "r"((b)[1]))

// ---------------- misc kernels ----------------------------------------------
__device__ __forceinline__ int load_idx(const void* base, long long i) {
    if (g_is64) return (int)((const long long*)base)[i];
    return ((const int*)base)[i];
}
__global__ void k_detect(const int* e32) {
    int is64 = 1;
    for (int i = 0; i < 32; i++)
        if (e32[2 * i + 1] != 0) is64 = 0;
    g_is64 = is64;
}
__global__ void k_zeroi(int* p, int n) {
    int i = blockIdx.x * blockDim.x + threadIdx.x;
    if (i < n) p[i] = 0;
}
__global__ void k_degi(const void* eidx) {
    int e = blockIdx.x * blockDim.x + threadIdx.x;
    if (e < EE) atomicAdd(&g_degi[load_idx(eidx, (long long)EE + e)], 1);
}
__global__ void k_scan1() {
    __shared__ int s[256];
    int i = blockIdx.x * 256 + threadIdx.x;
    int v = (i < NN) ? g_degi[i] : 0;
    s[threadIdx.x] = v;
    __syncthreads();
#pragma unroll
    for (int off = 1; off < 256; off <<= 1) {
        int t = (threadIdx.x >= off) ? s[threadIdx.x - off] : 0;
        __syncthreads();
        s[threadIdx.x] += t;
        __syncthreads();
    }
    if (i < NN) g_incl[i] = s[threadIdx.x];
    if (threadIdx.x == 255) g_bsum[blockIdx.x] = s[255];
}
__global__ void k_scan2() {
    __shared__ int s[512];
    int tid = threadIdx.x;
    s[tid] = (tid < NBLK1) ? g_bsum[tid] : 0;
    __syncthreads();
#pragma unroll
    for (int off = 1; off < 512; off <<= 1) {
        int t = (tid >= off) ? s[tid - off] : 0;
        __syncthreads();
        s[tid] += t;
        __syncthreads();
    }
    g_boff[tid] = s[tid];
}
__global__ void k_scan3() {
    int i = blockIdx.x * 256 + threadIdx.x;
    if (i < NN) {
        int off = (blockIdx.x > 0) ? g_boff[blockIdx.x - 1] : 0;
        int start = off + g_incl[i] - g_degi[i];
        g_rowptr[i] = start;
        g_cursor[i] = start;
    }
}
__global__ void k_fill(const void* eidx) {
    int e = blockIdx.x * blockDim.x + threadIdx.x;
    if (e < EE) {
        int s = load_idx(eidx, e);
        int d = load_idx(eidx, (long long)EE + e);
        g_csrc[atomicAdd(&g_cursor[d], 1)] = s;
    }
}

// gather mean aggregation, one warp per destination node
template <int VEC, bool ADD_EXTRA>
__global__ void k_agg(const float* __restrict__ feat,
                      const float* __restrict__ extra,
                      float* __restrict__ outp) {
    const int D = 32 * VEC;
    int warp = (blockIdx.x * blockDim.x + threadIdx.x) >> 5;
    int lane = threadIdx.x & 31;
    if (warp >= NN) return;
    int start = g_rowptr[warp];
    int dg = g_degi[warp];
    float acc[VEC];
#pragma unroll
    for (int v = 0; v < VEC; v++) acc[v] = 0.0f;
    for (int j = 0; j < dg; j++) {
        int s = g_csrc[start + j];
        const float* base = feat + (long long)s * D + lane;
#pragma unroll
        for (int v = 0; v < VEC; v++) acc[v] += base[v * 32];
    }
    float inv = (dg > 0) ? (1.0f / (float)dg) : 0.0f;
    float* op = outp + (long long)warp * D + lane;
    const float* ep = ADD_EXTRA ? (extra + (long long)warp * D + lane) : nullptr;
#pragma unroll
    for (int v = 0; v < VEC; v++) {
        float o = acc[v] * inv;
        if (ADD_EXTRA) o += ep[v * 32];
        op[v * 32] = o;
    }
}

// fp32 -> bf16 hi/lo split
__global__ void k_split(const float* __restrict__ in,
                        __nv_bfloat16* __restrict__ hi,
                        __nv_bfloat16* __restrict__ lo, long long n) {
    long long i = (long long)blockIdx.x * blockDim.x + threadIdx.x;
    long long stride = (long long)gridDim.x * blockDim.x;
    for (; i < n; i += stride) {
        float v = in[i];
        __nv_bfloat16 h = __float2bfloat16(v);
        hi[i] = h;
        lo[i] = __float2bfloat16(v - __bfloat162float(h));
    }
}

// W[K,N] fp32 -> Wt[N,K] bf16 hi/lo
__global__ void k_wsplit(const float* __restrict__ W,
                         __nv_bfloat16* __restrict__ th,
                         __nv_bfloat16* __restrict__ tl, int K, int N) {
    int i = blockIdx.x * blockDim.x + threadIdx.x;
    if (i < K * N) {
        int k = i / N, n = i % N;
        float v = W[i];
        __nv_bfloat16 h = __float2bfloat16(v);
        th[n * K + k] = h;
        tl[n * K + k] = __float2bfloat16(v - __bfloat162float(h));
    }
}

// ---------------- mma.sync bf16-split GEMM -----------------------------------
// C[128-tile, 64-tile] = sum_m A_m @ B_m^T with A,B bf16 hi/lo split
// (hh + hl + lh products), fp32 accumulate. BM=128 BN=64 BK=32, 8 warps (4x2),
// warp tile 32x32 = 2 m-atoms x 4 n-atoms of m16n8k16.
// DUAL: N=128 where cols [0,64) -> C1 (no bias), [64,128) -> C2 (+bias).
#define ASTR 40  // padded smem stride (bf16 units); conflict-free for ldmatrix
template <int KTOT, int NOUT, int NMAT, bool HAS_BIAS, bool BN, bool DUAL>
__global__ void __launch_bounds__(256) k_mgemm(
    const __nv_bfloat16* __restrict__ A1h, const __nv_bfloat16* __restrict__ A1l,
    const __nv_bfloat16* __restrict__ B1h, const __nv_bfloat16* __restrict__ B1l,
    const __nv_bfloat16* __restrict__ A2h, const __nv_bfloat16* __restrict__ A2l,
    const __nv_bfloat16* __restrict__ B2h, const __nv_bfloat16* __restrict__ B2l,
    const float* __restrict__ bias, const float* __restrict__ gamma,
    const float* __restrict__ beta, const float* __restrict__ rm,
    const float* __restrict__ rv, float* __restrict__ C1,
    float* __restrict__ C2) {
    __shared__ __align__(16) __nv_bfloat16 sAh[128 * ASTR];
    __shared__ __align__(16) __nv_bfloat16 sAl[128 * ASTR];
    __shared__ __align__(16) __nv_bfloat16 sBh[64 * ASTR];
    __shared__ __align__(16) __nv_bfloat16 sBl[64 * ASTR];

    const int tid = threadIdx.x;
    const int lane = tid & 31;
    const int wid = tid >> 5;
    const int wm = wid & 3;   // 4 m-warps
    const int wn = wid >> 2;  // 2 n-warps
    const long long bm = (long long)blockIdx.x * 128;
    const int bn = blockIdx.y * 64;

    float acc[2][4][4];
#pragma unroll
    for (int i = 0; i < 2; i++)
#pragma unroll
        for (int j = 0; j < 4; j++)
#pragma unroll
            for (int q = 0; q < 4; q++) acc[i][j][q] = 0.0f;

    // per-lane ldmatrix smem addresses (byte)
    const uint32_t aAh = smem_u32(sAh) +
        (((wm * 32 + (lane & 15)) * ASTR + ((lane >> 4) << 3)) << 1);
    const uint32_t aAl = smem_u32(sAl) +
        (((wm * 32 + (lane & 15)) * ASTR + ((lane >> 4) << 3)) << 1);
    const uint32_t aBh = smem_u32(sBh) +
        (((wn * 32 + (lane & 7)) * ASTR + (((lane >> 3) & 1) << 3)) << 1);
    const uint32_t aBl = smem_u32(sBl) +
        (((wn * 32 + (lane & 7)) * ASTR + (((lane >> 3) & 1) << 3)) << 1);

    for (int m = 0; m < NMAT; m++) {
        const __nv_bfloat16* Ah = (m == 0) ? A1h : A2h;
        const __nv_bfloat16* Al = (m == 0) ? A1l : A2l;
        const __nv_bfloat16* Bh = (m == 0) ? B1h : B2h;
        const __nv_bfloat16* Bl = (m == 0) ? B1l : B2l;

        for (int kc = 0; kc < KTOT / 32; kc++) {
            const int k0 = kc * 32;
            // A tiles: 128 rows x 32 bf16 (hi & lo)
#pragma unroll
            for (int idx = tid; idx < 512; idx += 256) {
                int r = idx >> 2, c = idx & 3;
                long long grow = bm + r;
                uint4 vh = make_uint4(0, 0, 0, 0), vl = vh;
                if (grow < NN) {
                    long long off = grow * KTOT + k0 + c * 8;
                    vh = *(const uint4*)(Ah + off);
                    vl = *(const uint4*)(Al + off);
                }
                *(uint4*)&sAh[r * ASTR + c * 8] = vh;
                *(uint4*)&sAl[r * ASTR + c * 8] = vl;
            }
            // B tiles: 64 rows x 32 bf16 (hi & lo)
            {
                int idx = tid;
                if (idx < 256) {
                    int r = idx >> 2, c = idx & 3;
                    long long off = (long long)(bn + r) * KTOT + k0 + c * 8;
                    *(uint4*)&sBh[r * ASTR + c * 8] = *(const uint4*)(Bh + off);
                    *(uint4*)&sBl[r * ASTR + c * 8] = *(const uint4*)(Bl + off);
                }
            }
            __syncthreads();

#pragma unroll
            for (int ka = 0; ka < 2; ka++) {
                const uint32_t ko = ka * 32;  // 16 bf16 = 32 bytes
                uint32_t ah[2][4], al[2][4], bh[4][2], bl[4][2];
                LDSM4(ah[0], aAh + ko);
                LDSM4(ah[1], aAh + 1280 + ko);  // +16 rows * 40 * 2B
                LDSM4(al[0], aAl + ko);
                LDSM4(al[1], aAl + 1280 + ko);
#pragma unroll
                for (int na = 0; na < 4; na++) {
                    LDSM2(bh[na], aBh + na * 640 + ko);  // +8 rows * 40 * 2B
                    LDSM2(bl[na], aBl + na * 640 + ko);
                }
#pragma unroll
                for (int ma = 0; ma < 2; ma++)
#pragma unroll
                    for (int na = 0; na < 4; na++) {
                        MMA16816(acc[ma][na], ah[ma], bh[na]);
                        MMA16816(acc[ma][na], ah[ma], bl[na]);
                        MMA16816(acc[ma][na], al[ma], bh[na]);
                    }
            }
            __syncthreads();
        }
    }

    // epilogue
    const int g = lane >> 2, t = lane & 3;
#pragma unroll
    for (int ma = 0; ma < 2; ma++) {
#pragma unroll
        for (int na = 0; na < 4; na++) {
            int lcol = wn * 32 + na * 8 + 2 * t;
            int gc = bn + lcol;
#pragma unroll
            for (int half = 0; half < 2; half++) {
                long long row = bm + wm * 32 + ma * 16 + g + half * 8;
                if (row >= NN) continue;
                float v0 = acc[ma][na][half * 2 + 0];
                float v1 = acc[ma][na][half * 2 + 1];
                if (DUAL) {
                    if (gc < 64) {
                        C1[row * 64 + gc] = v0;
                        C1[row * 64 + gc + 1] = v1;
                    } else {
                        C2[row * 64 + gc - 64] = v0 + bias[gc - 64];
                        C2[row * 64 + gc - 63] = v1 + bias[gc - 63];
                    }
                } else {
                    if (HAS_BIAS) { v0 += bias[gc]; v1 += bias[gc + 1]; }
                    if (BN) {
                        v0 = (v0 - rm[gc]) * rsqrtf(rv[gc] + FEPS) * gamma[gc] + beta[gc];
                        v1 = (v1 - rm[gc + 1]) * rsqrtf(rv[gc + 1] + FEPS) * gamma[gc + 1] + beta[gc + 1];
                        v0 = fmaxf(v0, 0.0f);
                        v1 = fmaxf(v1, 0.0f);
                    }
                    C1[row * NOUT + gc] = v0;
                    C1[row * NOUT + gc + 1] = v1;
                }
            }
        }
    }
}

// ---------------- launch ----------------------------------------------------
extern "C" void kernel_launch(void* const* d_in, const int* in_sizes, int n_in,
                              void* d_out, int out_size) {
    const float* x    = (const float*)d_in[0];
    const void*  eidx = d_in[1];
    const float* W1l  = (const float*)d_in[2];
    const float* b1l  = (const float*)d_in[3];
    const float* W1r  = (const float*)d_in[4];
    const float* g1   = (const float*)d_in[5];
    const float* be1  = (const float*)d_in[6];
    const float* rm1  = (const float*)d_in[7];
    const float* rv1  = (const float*)d_in[8];
    const float* W2l  = (const float*)d_in[9];
    const float* b2l  = (const float*)d_in[10];
    const float* W2r  = (const float*)d_in[11];
    const float* g2   = (const float*)d_in[12];
    const float* be2  = (const float*)d_in[13];
    const float* rm2  = (const float*)d_in[14];
    const float* rv2  = (const float*)d_in[15];
    const float* Wcl  = (const float*)d_in[16];
    const float* bcl  = (const float*)d_in[17];
    const float* Wcr  = (const float*)d_in[18];
    float* out = (float*)d_out;

    int* p_degi;        cudaGetSymbolAddress((void**)&p_degi, g_degi);
    float* p_msg;       cudaGetSymbolAddress((void**)&p_msg, g_msg);
    float* p_h1;        cudaGetSymbolAddress((void**)&p_h1, g_h1);
    float* p_h2;        cudaGetSymbolAddress((void**)&p_h2, g_h2);
    float* p_t;         cudaGetSymbolAddress((void**)&p_t, g_t);
    float* p_r;         cudaGetSymbolAddress((void**)&p_r, g_r);
    __nv_bfloat16* a1h; cudaGetSymbolAddress((void**)&a1h, g_a1h);
    __nv_bfloat16* a1l; cudaGetSymbolAddress((void**)&a1l, g_a1l);
    __nv_bfloat16* a2h; cudaGetSymbolAddress((void**)&a2h, g_a2h);
    __nv_bfloat16* a2l; cudaGetSymbolAddress((void**)&a2l, g_a2l);
    __nv_bfloat16* wh;  cudaGetSymbolAddress((void**)&wh, g_wh);
    __nv_bfloat16* wl;  cudaGetSymbolAddress((void**)&wl, g_wl);

    // 0) dtype detect + CSR build
    k_detect<<<1, 1>>>((const int*)eidx);
    k_zeroi<<<NBLK1, 256>>>(p_degi, NN);
    k_degi<<<(EE + 255) / 256, 256>>>(eidx);
    k_scan1<<<NBLK1, 256>>>();
    k_scan2<<<1, 512>>>();
    k_scan3<<<NBLK1, 256>>>();
    k_fill<<<(EE + 255) / 256, 256>>>(eidx);

    // 1) weight transpose + split
    k_wsplit<<<(INC * HIDC + 255) / 256, 256>>>(W1l, wh + WO_1L, wl + WO_1L, INC, HIDC);
    k_wsplit<<<(INC * HIDC + 255) / 256, 256>>>(W1r, wh + WO_1R, wl + WO_1R, INC, HIDC);
    k_wsplit<<<(HIDC * HIDC + 255) / 256, 256>>>(W2l, wh + WO_2L, wl + WO_2L, HIDC, HIDC);
    k_wsplit<<<(HIDC * HIDC + 255) / 256, 256>>>(W2r, wh + WO_2R, wl + WO_2R, HIDC, HIDC);
    k_wsplit<<<(HIDC * OUTC + 255) / 256, 256>>>(Wcl, wh + WO_CL, wl + WO_CL, HIDC, OUTC);
    k_wsplit<<<(HIDC * OUTC + 255) / 256, 256>>>(Wcr, wh + WO_CR, wl + WO_CR, HIDC, OUTC);

    const int MBLK = (NN + 127) / 128;  // 782
    const int AGG_BLOCKS = (NN + 7) / 8;

    // 2) layer 1: agg -> split -> GEMM(+BN+ReLU)
    k_agg<INC / 32, false><<<AGG_BLOCKS, 256>>>(x, nullptr, p_msg);
    k_split<<<4096, 256>>>(p_msg, a1h, a1l, (long long)NN * INC);
    k_split<<<4096, 256>>>(x, a2h, a2l, (long long)NN * INC);
    k_mgemm<INC, HIDC, 2, true, true, false><<<dim3(MBLK, HIDC / 64), 256>>>(
        a1h, a1l, wh + WO_1L, wl + WO_1L, a2h, a2l, wh + WO_1R, wl + WO_1R,
        b1l, g1, be1, rm1, rv1, p_h1, nullptr);

    // 3) layer 2
    k_agg<HIDC / 32, false><<<AGG_BLOCKS, 256>>>(p_h1, nullptr, p_msg);
    k_split<<<4096, 256>>>(p_msg, a1h, a1l, (long long)NN * HIDC);
    k_split<<<4096, 256>>>(p_h1, a2h, a2l, (long long)NN * HIDC);
    k_mgemm<HIDC, HIDC, 2, true, true, false><<<dim3(MBLK, HIDC / 64), 256>>>(
        a1h, a1l, wh + WO_2L, wl + WO_2L, a2h, a2l, wh + WO_2R, wl + WO_2R,
        b2l, g2, be2, rm2, rv2, p_h2, nullptr);

    // 4) layer 3: dual GEMM (t = h2@Wcl, r = h2@Wcr + bcl), then agg(t)+r
    k_split<<<4096, 256>>>(p_h2, a1h, a1l, (long long)NN * HIDC);
    k_mgemm<HIDC, 128, 1, true, false, true><<<dim3(MBLK, 2), 256>>>(
        a1h, a1l, wh + WO_CL, wl + WO_CL, nullptr, nullptr, nullptr, nullptr,
        bcl, nullptr, nullptr, nullptr, nullptr, p_t, p_r);
    k_agg<OUTC / 32, true><<<AGG_BLOCKS, 256>>>(p_t, p_r, out);
}

// round 5
// speedup vs baseline: 4.1312x; 1.2519x over previous
#include <cuda_runtime.h>
#include <cuda_bf16.h>
#include <cstdint>

#define NN 100000
#define EE 1600000
#define INC 128
#define HIDC 256
#define OUTC 64
#define FEPS 1e-5f
#define NBLK1 ((NN + 255) / 256)

// ---------------- scratch ----------------------------------------------------
__device__ int   g_is64;
__device__ int   g_degi[NN];
__device__ int   g_incl[NN];
__device__ int   g_bsum[512];
__device__ int   g_boff[512];
__device__ int   g_rowptr[NN];
__device__ int   g_cursor[NN];
__device__ int   g_csrc[EE];
__device__ float g_msg[(size_t)NN * HIDC];
__device__ float g_h1[(size_t)NN * HIDC];
__device__ float g_h2[(size_t)NN * HIDC];
__device__ float g_t[(size_t)NN * OUTC];
__device__ float g_r[(size_t)NN * OUTC];
// transposed, split weights, [N][K] layout. Wcl/Wcr contiguous -> one [128][256].
#define WO_1L 0
#define WO_1R 32768
#define WO_2L 65536
#define WO_2R 131072
#define WO_CL 196608
#define WO_CR 212992
__device__ __nv_bfloat16 g_wh[229376];
__device__ __nv_bfloat16 g_wl[229376];

// ---------------- PTX helpers ------------------------------------------------
__device__ __forceinline__ uint32_t smem_u32(const void* p) {
    uint32_t a;
    asm("{ .reg .u64 t; cvta.to.shared.u64 t, %1; cvt.u32.u64 %0, t; }"
        : "=r"(a) : "l"(p));
    return a;
}
#define LDSM4(r, addr)                                                          \
    asm volatile("ldmatrix.sync.aligned.m8n8.x4.shared.b16 {%0,%1,%2,%3}, [%4];"\
                 : "=r"((r)[0]), "=r"((r)[1]), "=r"((r)[2]), "=r"((r)[3])       \
                 : "r"(addr))
#define LDSM2(r, addr)                                                          \
    asm volatile("ldmatrix.sync.aligned.m8n8.x2.shared.b16 {%0,%1}, [%2];"      \
                 : "=r"((r)[0]), "=r"((r)[1]) : "r"(addr))
#define MMA16816(d, a, b)                                                       \
    asm volatile("mma.sync.aligned.m16n8k16.row.col.f32.bf16.bf16.f32 "         \
                 "{%0,%1,%2,%3}, {%4,%5,%6,%7}, {%8,%9}, {%0,%1,%2,%3};"        \
                 : "+f"((d)[0]), "+f"((d)[1]), "+f"((d)[2]), "+f"((d)[3])       \
                 : "r"((a)[0]), "r"((a)[1]), "r"((a)[2]), "r"((a)[3]),          \
                   "r"((b)[0]), "r"((b)[1]))

// ---------------- misc kernels ----------------------------------------------
__device__ __forceinline__ int load_idx(const void* base, long long i) {
    if (g_is64) return (int)((const long long*)base)[i];
    return ((const int*)base)[i];
}
__global__ void k_detect(const int* e32) {
    int is64 = 1;
    for (int i = 0; i < 32; i++)
        if (e32[2 * i + 1] != 0) is64 = 0;
    g_is64 = is64;
}
__global__ void k_zeroi(int* p, int n) {
    int i = blockIdx.x * blockDim.x + threadIdx.x;
    if (i < n) p[i] = 0;
}
__global__ void k_degi(const void* eidx) {
    int e = blockIdx.x * blockDim.x + threadIdx.x;
    if (e < EE) atomicAdd(&g_degi[load_idx(eidx, (long long)EE + e)], 1);
}
__global__ void k_scan1() {
    __shared__ int s[256];
    int i = blockIdx.x * 256 + threadIdx.x;
    int v = (i < NN) ? g_degi[i] : 0;
    s[threadIdx.x] = v;
    __syncthreads();
#pragma unroll
    for (int off = 1; off < 256; off <<= 1) {
        int t = (threadIdx.x >= off) ? s[threadIdx.x - off] : 0;
        __syncthreads();
        s[threadIdx.x] += t;
        __syncthreads();
    }
    if (i < NN) g_incl[i] = s[threadIdx.x];
    if (threadIdx.x == 255) g_bsum[blockIdx.x] = s[255];
}
__global__ void k_scan2() {
    __shared__ int s[512];
    int tid = threadIdx.x;
    s[tid] = (tid < NBLK1) ? g_bsum[tid] : 0;
    __syncthreads();
#pragma unroll
    for (int off = 1; off < 512; off <<= 1) {
        int t = (tid >= off) ? s[tid - off] : 0;
        __syncthreads();
        s[tid] += t;
        __syncthreads();
    }
    g_boff[tid] = s[tid];
}
__global__ void k_scan3() {
    int i = blockIdx.x * 256 + threadIdx.x;
    if (i < NN) {
        int off = (blockIdx.x > 0) ? g_boff[blockIdx.x - 1] : 0;
        int start = off + g_incl[i] - g_degi[i];
        g_rowptr[i] = start;
        g_cursor[i] = start;
    }
}
__global__ void k_fill(const void* eidx) {
    int e = blockIdx.x * blockDim.x + threadIdx.x;
    if (e < EE) {
        int s = load_idx(eidx, e);
        int d = load_idx(eidx, (long long)EE + e);
        g_csrc[atomicAdd(&g_cursor[d], 1)] = s;
    }
}

// gather mean aggregation, one warp per destination node
template <int VEC, bool ADD_EXTRA>
__global__ void k_agg(const float* __restrict__ feat,
                      const float* __restrict__ extra,
                      float* __restrict__ outp) {
    const int D = 32 * VEC;
    int warp = (blockIdx.x * blockDim.x + threadIdx.x) >> 5;
    int lane = threadIdx.x & 31;
    if (warp >= NN) return;
    int start = g_rowptr[warp];
    int dg = g_degi[warp];
    float acc[VEC];
#pragma unroll
    for (int v = 0; v < VEC; v++) acc[v] = 0.0f;
    int j = 0;
    for (; j + 2 <= dg; j += 2) {
        int s0 = g_csrc[start + j];
        int s1 = g_csrc[start + j + 1];
        const float* b0 = feat + (long long)s0 * D + lane;
        const float* b1 = feat + (long long)s1 * D + lane;
#pragma unroll
        for (int v = 0; v < VEC; v++) acc[v] += b0[v * 32];
#pragma unroll
        for (int v = 0; v < VEC; v++) acc[v] += b1[v * 32];
    }
    if (j < dg) {
        int s0 = g_csrc[start + j];
        const float* b0 = feat + (long long)s0 * D + lane;
#pragma unroll
        for (int v = 0; v < VEC; v++) acc[v] += b0[v * 32];
    }
    float inv = (dg > 0) ? (1.0f / (float)dg) : 0.0f;
    float* op = outp + (long long)warp * D + lane;
    const float* ep = ADD_EXTRA ? (extra + (long long)warp * D + lane) : nullptr;
#pragma unroll
    for (int v = 0; v < VEC; v++) {
        float o = acc[v] * inv;
        if (ADD_EXTRA) o += ep[v * 32];
        op[v * 32] = o;
    }
}

// W[K,N] fp32 -> Wt[N,K] bf16 hi/lo
__global__ void k_wsplit(const float* __restrict__ W,
                         __nv_bfloat16* __restrict__ th,
                         __nv_bfloat16* __restrict__ tl, int K, int N) {
    int i = blockIdx.x * blockDim.x + threadIdx.x;
    if (i < K * N) {
        int k = i / N, n = i % N;
        float v = W[i];
        __nv_bfloat16 h = __float2bfloat16(v);
        th[n * K + k] = h;
        tl[n * K + k] = __float2bfloat16(v - __bfloat162float(h));
    }
}

// ---------------- mma.sync bf16-split GEMM (A fp32, on-the-fly split) --------
// C[128-tile, 64-tile] = sum_m A_m @ B_m^T. A fp32 (split hi/lo during smem
// fill), B pre-split bf16 hi/lo. Products hh + hl + lh, fp32 accumulate.
// BM=128 BN=64 BK=32, 8 warps (4x2), warp tile 32x32.
// Register-prefetch: global loads for tile it+1 issued before compute of it.
#define ASTR 40
template <int KTOT, int NOUT, int NMAT, bool HAS_BIAS, bool BN, bool DUAL>
__global__ void __launch_bounds__(256) k_mgemm(
    const float* __restrict__ A1, const float* __restrict__ A2,
    const __nv_bfloat16* __restrict__ B1h, const __nv_bfloat16* __restrict__ B1l,
    const __nv_bfloat16* __restrict__ B2h, const __nv_bfloat16* __restrict__ B2l,
    const float* __restrict__ bias, const float* __restrict__ gamma,
    const float* __restrict__ beta, const float* __restrict__ rm,
    const float* __restrict__ rv, float* __restrict__ C1,
    float* __restrict__ C2) {
    __shared__ __align__(16) __nv_bfloat16 sAh[128 * ASTR];
    __shared__ __align__(16) __nv_bfloat16 sAl[128 * ASTR];
    __shared__ __align__(16) __nv_bfloat16 sBh[64 * ASTR];
    __shared__ __align__(16) __nv_bfloat16 sBl[64 * ASTR];

    const int tid = threadIdx.x;
    const int lane = tid & 31;
    const int wid = tid >> 5;
    const int wm = wid & 3;
    const int wn = wid >> 2;
    const long long bm = (long long)blockIdx.x * 128;
    const int bn = blockIdx.y * 64;
    const int KC = KTOT / 32;
    const int TOT = NMAT * KC;

    float acc[2][4][4];
#pragma unroll
    for (int i = 0; i < 2; i++)
#pragma unroll
        for (int j = 0; j < 4; j++)
#pragma unroll
            for (int q = 0; q < 4; q++) acc[i][j][q] = 0.0f;

    const uint32_t aAh = smem_u32(sAh) +
        (((wm * 32 + (lane & 15)) * ASTR + ((lane >> 4) << 3)) << 1);
    const uint32_t aAl = smem_u32(sAl) +
        (((wm * 32 + (lane & 15)) * ASTR + ((lane >> 4) << 3)) << 1);
    const uint32_t aBh = smem_u32(sBh) +
        (((wn * 32 + (lane & 7)) * ASTR + (((lane >> 3) & 1) << 3)) << 1);
    const uint32_t aBl = smem_u32(sBl) +
        (((wn * 32 + (lane & 7)) * ASTR + (((lane >> 3) & 1) << 3)) << 1);

    // prefetch registers
    float4 aR[4];
    uint4 bhR, blR;

#define LOAD_ITER(it) do {                                                       \
    int _m = (it) / KC, _kc = (it) % KC, _k0 = _kc * 32;                         \
    const float* _A = (_m == 0) ? A1 : A2;                                       \
    const __nv_bfloat16* _Bh = (_m == 0) ? B1h : B2h;                            \
    const __nv_bfloat16* _Bl = (_m == 0) ? B1l : B2l;                            \
    _Pragma("unroll")                                                            \
    for (int _i = 0; _i < 4; _i++) {                                             \
        int _s = tid + _i * 256;                                                 \
        int _r = _s >> 3, _c = _s & 7;                                           \
        long long _grow = bm + _r;                                               \
        float4 _v = make_float4(0.f, 0.f, 0.f, 0.f);                             \
        if (_grow < NN) _v = *(const float4*)(_A + _grow * KTOT + _k0 + _c * 4); \
        aR[_i] = _v;                                                             \
    }                                                                            \
    {                                                                            \
        int _r = tid >> 2, _c = tid & 3;                                         \
        long long _off = (long long)(bn + _r) * KTOT + _k0 + _c * 8;             \
        bhR = *(const uint4*)(_Bh + _off);                                       \
        blR = *(const uint4*)(_Bl + _off);                                       \
    }                                                                            \
} while (0)

#define STORE_ITER() do {                                                        \
    _Pragma("unroll")                                                            \
    for (int _i = 0; _i < 4; _i++) {                                             \
        int _s = tid + _i * 256;                                                 \
        int _r = _s >> 3, _c = _s & 7;                                           \
        float _f[4] = {aR[_i].x, aR[_i].y, aR[_i].z, aR[_i].w};                  \
        uint32_t _h01, _h23, _l01, _l23;                                         \
        {                                                                        \
            __nv_bfloat16 _h0 = __float2bfloat16(_f[0]);                         \
            __nv_bfloat16 _h1 = __float2bfloat16(_f[1]);                         \
            __nv_bfloat16 _h2 = __float2bfloat16(_f[2]);                         \
            __nv_bfloat16 _h3 = __float2bfloat16(_f[3]);                         \
            __nv_bfloat16 _l0 = __float2bfloat16(_f[0] - __bfloat162float(_h0)); \
            __nv_bfloat16 _l1 = __float2bfloat16(_f[1] - __bfloat162float(_h1)); \
            __nv_bfloat16 _l2 = __float2bfloat16(_f[2] - __bfloat162float(_h2)); \
            __nv_bfloat16 _l3 = __float2bfloat16(_f[3] - __bfloat162float(_h3)); \
            _h01 = ((uint32_t)__bfloat16_as_ushort(_h1) << 16) |                 \
                   __bfloat16_as_ushort(_h0);                                    \
            _h23 = ((uint32_t)__bfloat16_as_ushort(_h3) << 16) |                 \
                   __bfloat16_as_ushort(_h2);                                    \
            _l01 = ((uint32_t)__bfloat16_as_ushort(_l1) << 16) |                 \
                   __bfloat16_as_ushort(_l0);                                    \
            _l23 = ((uint32_t)__bfloat16_as_ushort(_l3) << 16) |                 \
                   __bfloat16_as_ushort(_l2);                                    \
        }                                                                        \
        *(uint2*)&sAh[_r * ASTR + _c * 4] = make_uint2(_h01, _h23);              \
        *(uint2*)&sAl[_r * ASTR + _c * 4] = make_uint2(_l01, _l23);              \
    }                                                                            \
    {                                                                            \
        int _r = tid >> 2, _c = tid & 3;                                         \
        *(uint4*)&sBh[_r * ASTR + _c * 8] = bhR;                                 \
        *(uint4*)&sBl[_r * ASTR + _c * 8] = blR;                                 \
    }                                                                            \
} while (0)

    LOAD_ITER(0);
    for (int it = 0; it < TOT; it++) {
        STORE_ITER();
        __syncthreads();
        if (it + 1 < TOT) LOAD_ITER(it + 1);

#pragma unroll
        for (int ka = 0; ka < 2; ka++) {
            const uint32_t ko = ka * 32;
            uint32_t ah[2][4], al[2][4], bh[4][2], bl[4][2];
            LDSM4(ah[0], aAh + ko);
            LDSM4(ah[1], aAh + 1280 + ko);
            LDSM4(al[0], aAl + ko);
            LDSM4(al[1], aAl + 1280 + ko);
#pragma unroll
            for (int na = 0; na < 4; na++) {
                LDSM2(bh[na], aBh + na * 640 + ko);
                LDSM2(bl[na], aBl + na * 640 + ko);
            }
#pragma unroll
            for (int ma = 0; ma < 2; ma++)
#pragma unroll
                for (int na = 0; na < 4; na++) {
                    MMA16816(acc[ma][na], ah[ma], bh[na]);
                    MMA16816(acc[ma][na], ah[ma], bl[na]);
                    MMA16816(acc[ma][na], al[ma], bh[na]);
                }
        }
        __syncthreads();
    }

    // epilogue
    const int g = lane >> 2, t = lane & 3;
#pragma unroll
    for (int ma = 0; ma < 2; ma++) {
#pragma unroll
        for (int na = 0; na < 4; na++) {
            int lcol = wn * 32 + na * 8 + 2 * t;
            int gc = bn + lcol;
#pragma unroll
            for (int half = 0; half < 2; half++) {
                long long row = bm + wm * 32 + ma * 16 + g + half * 8;
                if (row >= NN) continue;
                float v0 = acc[ma][na][half * 2 + 0];
                float v1 = acc[ma][na][half * 2 + 1];
                if (DUAL) {
                    if (gc < 64) {
                        C1[row * 64 + gc] = v0;
                        C1[row * 64 + gc + 1] = v1;
                    } else {
                        C2[row * 64 + gc - 64] = v0 + bias[gc - 64];
                        C2[row * 64 + gc - 63] = v1 + bias[gc - 63];
                    }
                } else {
                    if (HAS_BIAS) { v0 += bias[gc]; v1 += bias[gc + 1]; }
                    if (BN) {
                        v0 = (v0 - rm[gc]) * rsqrtf(rv[gc] + FEPS) * gamma[gc] + beta[gc];
                        v1 = (v1 - rm[gc + 1]) * rsqrtf(rv[gc + 1] + FEPS) * gamma[gc + 1] + beta[gc + 1];
                        v0 = fmaxf(v0, 0.0f);
                        v1 = fmaxf(v1, 0.0f);
                    }
                    C1[row * NOUT + gc] = v0;
                    C1[row * NOUT + gc + 1] = v1;
                }
            }
        }
    }
#undef LOAD_ITER
#undef STORE_ITER
}

// ---------------- launch ----------------------------------------------------
extern "C" void kernel_launch(void* const* d_in, const int* in_sizes, int n_in,
                              void* d_out, int out_size) {
    const float* x    = (const float*)d_in[0];
    const void*  eidx = d_in[1];
    const float* W1l  = (const float*)d_in[2];
    const float* b1l  = (const float*)d_in[3];
    const float* W1r  = (const float*)d_in[4];
    const float* g1   = (const float*)d_in[5];
    const float* be1  = (const float*)d_in[6];
    const float* rm1  = (const float*)d_in[7];
    const float* rv1  = (const float*)d_in[8];
    const float* W2l  = (const float*)d_in[9];
    const float* b2l  = (const float*)d_in[10];
    const float* W2r  = (const float*)d_in[11];
    const float* g2   = (const float*)d_in[12];
    const float* be2  = (const float*)d_in[13];
    const float* rm2  = (const float*)d_in[14];
    const float* rv2  = (const float*)d_in[15];
    const float* Wcl  = (const float*)d_in[16];
    const float* bcl  = (const float*)d_in[17];
    const float* Wcr  = (const float*)d_in[18];
    float* out = (float*)d_out;

    int* p_degi;        cudaGetSymbolAddress((void**)&p_degi, g_degi);
    float* p_msg;       cudaGetSymbolAddress((void**)&p_msg, g_msg);
    float* p_h1;        cudaGetSymbolAddress((void**)&p_h1, g_h1);
    float* p_h2;        cudaGetSymbolAddress((void**)&p_h2, g_h2);
    float* p_t;         cudaGetSymbolAddress((void**)&p_t, g_t);
    float* p_r;         cudaGetSymbolAddress((void**)&p_r, g_r);
    __nv_bfloat16* wh;  cudaGetSymbolAddress((void**)&wh, g_wh);
    __nv_bfloat16* wl;  cudaGetSymbolAddress((void**)&wl, g_wl);

    // 0) dtype detect + CSR build
    k_detect<<<1, 1>>>((const int*)eidx);
    k_zeroi<<<NBLK1, 256>>>(p_degi, NN);
    k_degi<<<(EE + 255) / 256, 256>>>(eidx);
    k_scan1<<<NBLK1, 256>>>();
    k_scan2<<<1, 512>>>();
    k_scan3<<<NBLK1, 256>>>();
    k_fill<<<(EE + 255) / 256, 256>>>(eidx);

    // 1) weight transpose + split
    k_wsplit<<<(INC * HIDC + 255) / 256, 256>>>(W1l, wh + WO_1L, wl + WO_1L, INC, HIDC);
    k_wsplit<<<(INC * HIDC + 255) / 256, 256>>>(W1r, wh + WO_1R, wl + WO_1R, INC, HIDC);
    k_wsplit<<<(HIDC * HIDC + 255) / 256, 256>>>(W2l, wh + WO_2L, wl + WO_2L, HIDC, HIDC);
    k_wsplit<<<(HIDC * HIDC + 255) / 256, 256>>>(W2r, wh + WO_2R, wl + WO_2R, HIDC, HIDC);
    k_wsplit<<<(HIDC * OUTC + 255) / 256, 256>>>(Wcl, wh + WO_CL, wl + WO_CL, HIDC, OUTC);
    k_wsplit<<<(HIDC * OUTC + 255) / 256, 256>>>(Wcr, wh + WO_CR, wl + WO_CR, HIDC, OUTC);

    const int MBLK = (NN + 127) / 128;  // 782
    const int AGG_BLOCKS = (NN + 7) / 8;

    // 2) layer 1: agg -> GEMM(+BN+ReLU); A operands fp32, split in-kernel
    k_agg<INC / 32, false><<<AGG_BLOCKS, 256>>>(x, nullptr, p_msg);
    k_mgemm<INC, HIDC, 2, true, true, false><<<dim3(MBLK, HIDC / 64), 256>>>(
        p_msg, x, wh + WO_1L, wl + WO_1L, wh + WO_1R, wl + WO_1R,
        b1l, g1, be1, rm1, rv1, p_h1, nullptr);

    // 3) layer 2
    k_agg<HIDC / 32, false><<<AGG_BLOCKS, 256>>>(p_h1, nullptr, p_msg);
    k_mgemm<HIDC, HIDC, 2, true, true, false><<<dim3(MBLK, HIDC / 64), 256>>>(
        p_msg, p_h1, wh + WO_2L, wl + WO_2L, wh + WO_2R, wl + WO_2R,
        b2l, g2, be2, rm2, rv2, p_h2, nullptr);

    // 4) layer 3: dual GEMM (t = h2@Wcl, r = h2@Wcr + bcl), then out = agg(t)+r
    k_mgemm<HIDC, 128, 1, true, false, true><<<dim3(MBLK, 2), 256>>>(
        p_h2, nullptr, wh + WO_CL, wl + WO_CL, nullptr, nullptr,
        bcl, nullptr, nullptr, nullptr, nullptr, p_t, p_r);
    k_agg<OUTC / 32, true><<<AGG_BLOCKS, 256>>>(p_t, p_r, out);
}

// round 6
// speedup vs baseline: 4.3287x; 1.0478x over previous
#include <cuda_runtime.h>
#include <cuda_bf16.h>
#include <cstdint>

#define NN 100000
#define EE 1600000
#define INC 128
#define HIDC 256
#define OUTC 64
#define FEPS 1e-5f
#define NBLK1 ((NN + 255) / 256)

// ---------------- scratch ----------------------------------------------------
__device__ int   g_is64;
__device__ int   g_degi[NN];
__device__ int   g_incl[NN];
__device__ int   g_bsum[512];
__device__ int   g_boff[512];
__device__ int   g_rowptr[NN];
__device__ int   g_cursor[NN];
__device__ int   g_csrc[EE];
__device__ float g_msg[(size_t)NN * HIDC];
__device__ float g_h1[(size_t)NN * HIDC];
__device__ float g_h2[(size_t)NN * HIDC];
__device__ float g_t[(size_t)NN * OUTC];
__device__ float g_r[(size_t)NN * OUTC];
// transposed, split weights, [N][K] layout. Wcl/Wcr contiguous -> one [128][256].
#define WO_1L 0
#define WO_1R 32768
#define WO_2L 65536
#define WO_2R 131072
#define WO_CL 196608
#define WO_CR 212992
__device__ __nv_bfloat16 g_wh[229376];
__device__ __nv_bfloat16 g_wl[229376];

// ---------------- PTX helpers ------------------------------------------------
__device__ __forceinline__ uint32_t smem_u32(const void* p) {
    uint32_t a;
    asm("{ .reg .u64 t; cvta.to.shared.u64 t, %1; cvt.u32.u64 %0, t; }"
        : "=r"(a) : "l"(p));
    return a;
}
#define LDSM4(r, addr)                                                          \
    asm volatile("ldmatrix.sync.aligned.m8n8.x4.shared.b16 {%0,%1,%2,%3}, [%4];"\
                 : "=r"((r)[0]), "=r"((r)[1]), "=r"((r)[2]), "=r"((r)[3])       \
                 : "r"(addr))
#define LDSM2(r, addr)                                                          \
    asm volatile("ldmatrix.sync.aligned.m8n8.x2.shared.b16 {%0,%1}, [%2];"      \
                 : "=r"((r)[0]), "=r"((r)[1]) : "r"(addr))
#define MMA16816(d, a, b)                                                       \
    asm volatile("mma.sync.aligned.m16n8k16.row.col.f32.bf16.bf16.f32 "         \
                 "{%0,%1,%2,%3}, {%4,%5,%6,%7}, {%8,%9}, {%0,%1,%2,%3};"        \
                 : "+f"((d)[0]), "+f"((d)[1]), "+f"((d)[2]), "+f"((d)[3])       \
                 : "r"((a)[0]), "r"((a)[1]), "r"((a)[2]), "r"((a)[3]),          \
                   "r"((b)[0]), "r"((b)[1]))

// ---------------- misc kernels ----------------------------------------------
__device__ __forceinline__ int load_idx(const void* base, long long i) {
    if (g_is64) return (int)((const long long*)base)[i];
    return ((const int*)base)[i];
}
__global__ void k_detect(const int* e32) {
    int is64 = 1;
    for (int i = 0; i < 32; i++)
        if (e32[2 * i + 1] != 0) is64 = 0;
    g_is64 = is64;
}
__global__ void k_zeroi(int* p, int n) {
    int i = blockIdx.x * blockDim.x + threadIdx.x;
    if (i < n) p[i] = 0;
}
__global__ void k_degi(const void* eidx) {
    int e = blockIdx.x * blockDim.x + threadIdx.x;
    if (e < EE) atomicAdd(&g_degi[load_idx(eidx, (long long)EE + e)], 1);
}
__global__ void k_scan1() {
    __shared__ int s[256];
    int i = blockIdx.x * 256 + threadIdx.x;
    int v = (i < NN) ? g_degi[i] : 0;
    s[threadIdx.x] = v;
    __syncthreads();
#pragma unroll
    for (int off = 1; off < 256; off <<= 1) {
        int t = (threadIdx.x >= off) ? s[threadIdx.x - off] : 0;
        __syncthreads();
        s[threadIdx.x] += t;
        __syncthreads();
    }
    if (i < NN) g_incl[i] = s[threadIdx.x];
    if (threadIdx.x == 255) g_bsum[blockIdx.x] = s[255];
}
__global__ void k_scan2() {
    __shared__ int s[512];
    int tid = threadIdx.x;
    s[tid] = (tid < NBLK1) ? g_bsum[tid] : 0;
    __syncthreads();
#pragma unroll
    for (int off = 1; off < 512; off <<= 1) {
        int t = (tid >= off) ? s[tid - off] : 0;
        __syncthreads();
        s[tid] += t;
        __syncthreads();
    }
    g_boff[tid] = s[tid];
}
__global__ void k_scan3() {
    int i = blockIdx.x * 256 + threadIdx.x;
    if (i < NN) {
        int off = (blockIdx.x > 0) ? g_boff[blockIdx.x - 1] : 0;
        int start = off + g_incl[i] - g_degi[i];
        g_rowptr[i] = start;
        g_cursor[i] = start;
    }
}
__global__ void k_fill(const void* eidx) {
    int e = blockIdx.x * blockDim.x + threadIdx.x;
    if (e < EE) {
        int s = load_idx(eidx, e);
        int d = load_idx(eidx, (long long)EE + e);
        g_csrc[atomicAdd(&g_cursor[d], 1)] = s;
    }
}

// ---------------- gather mean aggregation ------------------------------------
// One warp per destination node; lane owns CH contiguous channels
// [lane*CH, lane*CH+CH). Vector loads (float2/float4), 4 neighbors in flight.
template <int CH>
__device__ __forceinline__ void vload(float (&r)[CH], const float* p) {
    if (CH == 2) {
        float2 v = *(const float2*)p;
        r[0] = v.x;
        r[1] = v.y;
    } else {
#pragma unroll
        for (int q = 0; q < CH / 4; q++) {
            float4 v = *(const float4*)(p + q * 4);
            r[q * 4 + 0] = v.x;
            r[q * 4 + 1] = v.y;
            r[q * 4 + 2] = v.z;
            r[q * 4 + 3] = v.w;
        }
    }
}
template <int CH>
__device__ __forceinline__ void vstore(float* p, const float (&r)[CH]) {
    if (CH == 2) {
        *(float2*)p = make_float2(r[0], r[1]);
    } else {
#pragma unroll
        for (int q = 0; q < CH / 4; q++)
            *(float4*)(p + q * 4) =
                make_float4(r[q * 4 + 0], r[q * 4 + 1], r[q * 4 + 2], r[q * 4 + 3]);
    }
}

template <int CH, bool ADD_EXTRA>
__global__ void k_agg(const float* __restrict__ feat,
                      const float* __restrict__ extra,
                      float* __restrict__ outp) {
    const int D = 32 * CH;
    int warp = (blockIdx.x * blockDim.x + threadIdx.x) >> 5;
    int lane = threadIdx.x & 31;
    if (warp >= NN) return;
    int start = g_rowptr[warp];
    int dg = g_degi[warp];
    const float* fb = feat + lane * CH;

    float acc[CH];
#pragma unroll
    for (int v = 0; v < CH; v++) acc[v] = 0.0f;

    int j = 0;
    for (; j + 4 <= dg; j += 4) {
        int s0 = g_csrc[start + j + 0];
        int s1 = g_csrc[start + j + 1];
        int s2 = g_csrc[start + j + 2];
        int s3 = g_csrc[start + j + 3];
        float r0[CH], r1[CH], r2[CH], r3[CH];
        vload<CH>(r0, fb + (long long)s0 * D);
        vload<CH>(r1, fb + (long long)s1 * D);
        vload<CH>(r2, fb + (long long)s2 * D);
        vload<CH>(r3, fb + (long long)s3 * D);
#pragma unroll
        for (int v = 0; v < CH; v++) acc[v] += r0[v];
#pragma unroll
        for (int v = 0; v < CH; v++) acc[v] += r1[v];
#pragma unroll
        for (int v = 0; v < CH; v++) acc[v] += r2[v];
#pragma unroll
        for (int v = 0; v < CH; v++) acc[v] += r3[v];
    }
    for (; j < dg; j++) {
        int s0 = g_csrc[start + j];
        float r0[CH];
        vload<CH>(r0, fb + (long long)s0 * D);
#pragma unroll
        for (int v = 0; v < CH; v++) acc[v] += r0[v];
    }

    float inv = (dg > 0) ? (1.0f / (float)dg) : 0.0f;
    float* op = outp + (long long)warp * D + lane * CH;
#pragma unroll
    for (int v = 0; v < CH; v++) acc[v] *= inv;
    if (ADD_EXTRA) {
        float ex[CH];
        vload<CH>(ex, extra + (long long)warp * D + lane * CH);
#pragma unroll
        for (int v = 0; v < CH; v++) acc[v] += ex[v];
    }
    vstore<CH>(op, acc);
}

// W[K,N] fp32 -> Wt[N,K] bf16 hi/lo
__global__ void k_wsplit(const float* __restrict__ W,
                         __nv_bfloat16* __restrict__ th,
                         __nv_bfloat16* __restrict__ tl, int K, int N) {
    int i = blockIdx.x * blockDim.x + threadIdx.x;
    if (i < K * N) {
        int k = i / N, n = i % N;
        float v = W[i];
        __nv_bfloat16 h = __float2bfloat16(v);
        th[n * K + k] = h;
        tl[n * K + k] = __float2bfloat16(v - __bfloat162float(h));
    }
}

// ---------------- mma.sync bf16-split GEMM, double-buffered smem -------------
// C[128-tile, 64-tile] = sum_m A_m @ B_m^T. A fp32 (split hi/lo in the smem
// fill), B pre-split bf16 hi/lo. Products hh + hl + lh, fp32 accumulate.
// BM=128 BN=64 BK=32, 8 warps (4x2), warp tile 32x32. 2-stage smem pipeline.
#define ASTR 40
// byte offsets within one buffer (bf16 elems *2)
#define OAH 0
#define OAL 10240        // 128*ASTR*2
#define OBH 20480        // 256*ASTR*2
#define OBL 25600        // 320*ASTR*2
#define BUFB 30720       // 384*ASTR*2 bytes per stage
template <int KTOT, int NOUT, int NMAT, bool HAS_BIAS, bool BN, bool DUAL>
__global__ void __launch_bounds__(256) k_mgemm(
    const float* __restrict__ A1, const float* __restrict__ A2,
    const __nv_bfloat16* __restrict__ B1h, const __nv_bfloat16* __restrict__ B1l,
    const __nv_bfloat16* __restrict__ B2h, const __nv_bfloat16* __restrict__ B2l,
    const float* __restrict__ bias, const float* __restrict__ gamma,
    const float* __restrict__ beta, const float* __restrict__ rm,
    const float* __restrict__ rv, float* __restrict__ C1,
    float* __restrict__ C2) {
    extern __shared__ __align__(16) char dsm[];

    const int tid = threadIdx.x;
    const int lane = tid & 31;
    const int wid = tid >> 5;
    const int wm = wid & 3;
    const int wn = wid >> 2;
    const long long bm = (long long)blockIdx.x * 128;
    const int bn = blockIdx.y * 64;
    const int KC = KTOT / 32;
    const int TOT = NMAT * KC;

    float acc[2][4][4];
#pragma unroll
    for (int i = 0; i < 2; i++)
#pragma unroll
        for (int j = 0; j < 4; j++)
#pragma unroll
            for (int q = 0; q < 4; q++) acc[i][j][q] = 0.0f;

    const uint32_t sb = smem_u32(dsm);
    const uint32_t loA = (((wm * 32 + (lane & 15)) * ASTR + ((lane >> 4) << 3)) << 1);
    const uint32_t loB = (((wn * 32 + (lane & 7)) * ASTR + (((lane >> 3) & 1) << 3)) << 1);

    float4 aR[4];
    uint4 bhR, blR;

#define LOAD_ITER(it) do {                                                       \
    int _m = (it) / KC, _kc = (it) % KC, _k0 = _kc * 32;                         \
    const float* _A = (_m == 0) ? A1 : A2;                                       \
    const __nv_bfloat16* _Bh = (_m == 0) ? B1h : B2h;                            \
    const __nv_bfloat16* _Bl = (_m == 0) ? B1l : B2l;                            \
    _Pragma("unroll")                                                            \
    for (int _i = 0; _i < 4; _i++) {                                             \
        int _s = tid + _i * 256;                                                 \
        int _r = _s >> 3, _c = _s & 7;                                           \
        long long _grow = bm + _r;                                               \
        float4 _v = make_float4(0.f, 0.f, 0.f, 0.f);                             \
        if (_grow < NN) _v = *(const float4*)(_A + _grow * KTOT + _k0 + _c * 4); \
        aR[_i] = _v;                                                             \
    }                                                                            \
    {                                                                            \
        int _r = tid >> 2, _c = tid & 3;                                         \
        long long _off = (long long)(bn + _r) * KTOT + _k0 + _c * 8;             \
        bhR = *(const uint4*)(_Bh + _off);                                       \
        blR = *(const uint4*)(_Bl + _off);                                       \
    }                                                                            \
} while (0)

#define STORE_ITER(buf) do {                                                     \
    char* _S = dsm + (buf) * BUFB;                                               \
    _Pragma("unroll")                                                            \
    for (int _i = 0; _i < 4; _i++) {                                             \
        int _s = tid + _i * 256;                                                 \
        int _r = _s >> 3, _c = _s & 7;                                           \
        float _f[4] = {aR[_i].x, aR[_i].y, aR[_i].z, aR[_i].w};                  \
        uint32_t _h01, _h23, _l01, _l23;                                         \
        {                                                                        \
            __nv_bfloat16 _h0 = __float2bfloat16(_f[0]);                         \
            __nv_bfloat16 _h1 = __float2bfloat16(_f[1]);                         \
            __nv_bfloat16 _h2 = __float2bfloat16(_f[2]);                         \
            __nv_bfloat16 _h3 = __float2bfloat16(_f[3]);                         \
            __nv_bfloat16 _l0 = __float2bfloat16(_f[0] - __bfloat162float(_h0)); \
            __nv_bfloat16 _l1 = __float2bfloat16(_f[1] - __bfloat162float(_h1)); \
            __nv_bfloat16 _l2 = __float2bfloat16(_f[2] - __bfloat162float(_h2)); \
            __nv_bfloat16 _l3 = __float2bfloat16(_f[3] - __bfloat162float(_h3)); \
            _h01 = ((uint32_t)__bfloat16_as_ushort(_h1) << 16) |                 \
                   __bfloat16_as_ushort(_h0);                                    \
            _h23 = ((uint32_t)__bfloat16_as_ushort(_h3) << 16) |                 \
                   __bfloat16_as_ushort(_h2);                                    \
            _l01 = ((uint32_t)__bfloat16_as_ushort(_l1) << 16) |                 \
                   __bfloat16_as_ushort(_l0);                                    \
            _l23 = ((uint32_t)__bfloat16_as_ushort(_l3) << 16) |                 \
                   __bfloat16_as_ushort(_l2);                                    \
        }                                                                        \
        *(uint2*)(_S + OAH + (_r * ASTR + _c * 4) * 2) = make_uint2(_h01, _h23); \
        *(uint2*)(_S + OAL + (_r * ASTR + _c * 4) * 2) = make_uint2(_l01, _l23); \
    }                                                                            \
    {                                                                            \
        int _r = tid >> 2, _c = tid & 3;                                         \
        *(uint4*)(_S + OBH + (_r * ASTR + _c * 8) * 2) = bhR;                    \
        *(uint4*)(_S + OBL + (_r * ASTR + _c * 8) * 2) = blR;                    \
    }                                                                            \
} while (0)

#define COMPUTE(buf) do {                                                        \
    const uint32_t _b = sb + (buf) * BUFB;                                       \
    const uint32_t _aAh = _b + OAH + loA;                                        \
    const uint32_t _aAl = _b + OAL + loA;                                        \
    const uint32_t _aBh = _b + OBH + loB;                                        \
    const uint32_t _aBl = _b + OBL + loB;                                        \
    _Pragma("unroll")                                                            \
    for (int _ka = 0; _ka < 2; _ka++) {                                          \
        const uint32_t _ko = _ka * 32;                                           \
        uint32_t _ah[2][4], _al[2][4], _bh[4][2], _bl[4][2];                     \
        LDSM4(_ah[0], _aAh + _ko);                                               \
        LDSM4(_ah[1], _aAh + 1280 + _ko);                                        \
        LDSM4(_al[0], _aAl + _ko);                                               \
        LDSM4(_al[1], _aAl + 1280 + _ko);                                        \
        _Pragma("unroll")                                                        \
        for (int _na = 0; _na < 4; _na++) {                                      \
            LDSM2(_bh[_na], _aBh + _na * 640 + _ko);                             \
            LDSM2(_bl[_na], _aBl + _na * 640 + _ko);                             \
        }                                                                        \
        _Pragma("unroll")                                                        \
        for (int _ma = 0; _ma < 2; _ma++)                                        \
            _Pragma("unroll")                                                    \
            for (int _na = 0; _na < 4; _na++) {                                  \
                MMA16816(acc[_ma][_na], _ah[_ma], _bh[_na]);                     \
                MMA16816(acc[_ma][_na], _ah[_ma], _bl[_na]);                     \
                MMA16816(acc[_ma][_na], _al[_ma], _bh[_na]);                     \
            }                                                                    \
    }                                                                            \
} while (0)

    LOAD_ITER(0);
    STORE_ITER(0);
    __syncthreads();
    for (int it = 0; it < TOT; it++) {
        const int cur = it & 1;
        if (it + 1 < TOT) LOAD_ITER(it + 1);
        COMPUTE(cur);
        if (it + 1 < TOT) STORE_ITER(cur ^ 1);
        __syncthreads();
    }

    // epilogue
    const int g = lane >> 2, t = lane & 3;
#pragma unroll
    for (int ma = 0; ma < 2; ma++) {
#pragma unroll
        for (int na = 0; na < 4; na++) {
            int lcol = wn * 32 + na * 8 + 2 * t;
            int gc = bn + lcol;
#pragma unroll
            for (int half = 0; half < 2; half++) {
                long long row = bm + wm * 32 + ma * 16 + g + half * 8;
                if (row >= NN) continue;
                float v0 = acc[ma][na][half * 2 + 0];
                float v1 = acc[ma][na][half * 2 + 1];
                if (DUAL) {
                    if (gc < 64) {
                        C1[row * 64 + gc] = v0;
                        C1[row * 64 + gc + 1] = v1;
                    } else {
                        C2[row * 64 + gc - 64] = v0 + bias[gc - 64];
                        C2[row * 64 + gc - 63] = v1 + bias[gc - 63];
                    }
                } else {
                    if (HAS_BIAS) { v0 += bias[gc]; v1 += bias[gc + 1]; }
                    if (BN) {
                        v0 = (v0 - rm[gc]) * rsqrtf(rv[gc] + FEPS) * gamma[gc] + beta[gc];
                        v1 = (v1 - rm[gc + 1]) * rsqrtf(rv[gc + 1] + FEPS) * gamma[gc + 1] + beta[gc + 1];
                        v0 = fmaxf(v0, 0.0f);
                        v1 = fmaxf(v1, 0.0f);
                    }
                    C1[row * NOUT + gc] = v0;
                    C1[row * NOUT + gc + 1] = v1;
                }
            }
        }
    }
#undef LOAD_ITER
#undef STORE_ITER
#undef COMPUTE
}

// ---------------- launch ----------------------------------------------------
extern "C" void kernel_launch(void* const* d_in, const int* in_sizes, int n_in,
                              void* d_out, int out_size) {
    const float* x    = (const float*)d_in[0];
    const void*  eidx = d_in[1];
    const float* W1l  = (const float*)d_in[2];
    const float* b1l  = (const float*)d_in[3];
    const float* W1r  = (const float*)d_in[4];
    const float* g1   = (const float*)d_in[5];
    const float* be1  = (const float*)d_in[6];
    const float* rm1  = (const float*)d_in[7];
    const float* rv1  = (const float*)d_in[8];
    const float* W2l  = (const float*)d_in[9];
    const float* b2l  = (const float*)d_in[10];
    const float* W2r  = (const float*)d_in[11];
    const float* g2   = (const float*)d_in[12];
    const float* be2  = (const float*)d_in[13];
    const float* rm2  = (const float*)d_in[14];
    const float* rv2  = (const float*)d_in[15];
    const float* Wcl  = (const float*)d_in[16];
    const float* bcl  = (const float*)d_in[17];
    const float* Wcr  = (const float*)d_in[18];
    float* out = (float*)d_out;

    int* p_degi;        cudaGetSymbolAddress((void**)&p_degi, g_degi);
    float* p_msg;       cudaGetSymbolAddress((void**)&p_msg, g_msg);
    float* p_h1;        cudaGetSymbolAddress((void**)&p_h1, g_h1);
    float* p_h2;        cudaGetSymbolAddress((void**)&p_h2, g_h2);
    float* p_t;         cudaGetSymbolAddress((void**)&p_t, g_t);
    float* p_r;         cudaGetSymbolAddress((void**)&p_r, g_r);
    __nv_bfloat16* wh;  cudaGetSymbolAddress((void**)&wh, g_wh);
    __nv_bfloat16* wl;  cudaGetSymbolAddress((void**)&wl, g_wl);

    const int DSMEM = 2 * BUFB;  // 61440
    cudaFuncSetAttribute(k_mgemm<INC, HIDC, 2, true, true, false>,
                         cudaFuncAttributeMaxDynamicSharedMemorySize, DSMEM);
    cudaFuncSetAttribute(k_mgemm<HIDC, HIDC, 2, true, true, false>,
                         cudaFuncAttributeMaxDynamicSharedMemorySize, DSMEM);
    cudaFuncSetAttribute(k_mgemm<HIDC, 128, 1, true, false, true>,
                         cudaFuncAttributeMaxDynamicSharedMemorySize, DSMEM);

    // 0) dtype detect + CSR build
    k_detect<<<1, 1>>>((const int*)eidx);
    k_zeroi<<<NBLK1, 256>>>(p_degi, NN);
    k_degi<<<(EE + 255) / 256, 256>>>(eidx);
    k_scan1<<<NBLK1, 256>>>();
    k_scan2<<<1, 512>>>();
    k_scan3<<<NBLK1, 256>>>();
    k_fill<<<(EE + 255) / 256, 256>>>(eidx);

    // 1) weight transpose + split
    k_wsplit<<<(INC * HIDC + 255) / 256, 256>>>(W1l, wh + WO_1L, wl + WO_1L, INC, HIDC);
    k_wsplit<<<(INC * HIDC + 255) / 256, 256>>>(W1r, wh + WO_1R, wl + WO_1R, INC, HIDC);
    k_wsplit<<<(HIDC * HIDC + 255) / 256, 256>>>(W2l, wh + WO_2L, wl + WO_2L, HIDC, HIDC);
    k_wsplit<<<(HIDC * HIDC + 255) / 256, 256>>>(W2r, wh + WO_2R, wl + WO_2R, HIDC, HIDC);
    k_wsplit<<<(HIDC * OUTC + 255) / 256, 256>>>(Wcl, wh + WO_CL, wl + WO_CL, HIDC, OUTC);
    k_wsplit<<<(HIDC * OUTC + 255) / 256, 256>>>(Wcr, wh + WO_CR, wl + WO_CR, HIDC, OUTC);

    const int MBLK = (NN + 127) / 128;  // 782
    const int AGG_BLOCKS = (NN + 7) / 8;

    // 2) layer 1: agg -> GEMM(+BN+ReLU)
    k_agg<INC / 32, false><<<AGG_BLOCKS, 256>>>(x, nullptr, p_msg);
    k_mgemm<INC, HIDC, 2, true, true, false><<<dim3(MBLK, HIDC / 64), 256, DSMEM>>>(
        p_msg, x, wh + WO_1L, wl + WO_1L, wh + WO_1R, wl + WO_1R,
        b1l, g1, be1, rm1, rv1, p_h1, nullptr);

    // 3) layer 2
    k_agg<HIDC / 32, false><<<AGG_BLOCKS, 256>>>(p_h1, nullptr, p_msg);
    k_mgemm<HIDC, HIDC, 2, true, true, false><<<dim3(MBLK, HIDC / 64), 256, DSMEM>>>(
        p_msg, p_h1, wh + WO_2L, wl + WO_2L, wh + WO_2R, wl + WO_2R,
        b2l, g2, be2, rm2, rv2, p_h2, nullptr);

    // 4) layer 3: dual GEMM (t = h2@Wcl, r = h2@Wcr + bcl), then out = agg(t)+r
    k_mgemm<HIDC, 128, 1, true, false, true><<<dim3(MBLK, 2), 256, DSMEM>>>(
        p_h2, nullptr, wh + WO_CL, wl + WO_CL, nullptr, nullptr,
        bcl, nullptr, nullptr, nullptr, nullptr, p_t, p_r);
    k_agg<OUTC / 32, true><<<AGG_BLOCKS, 256>>>(p_t, p_r, out);
}